// round 1
// baseline (speedup 1.0000x reference)
#include <cuda_runtime.h>

#define BB   32
#define NN   2048
#define FF   3
#define HH   64
#define OUTD 128
#define KK   16

// ---------------- scratch (static device globals; no runtime allocation) ----
__device__ float g_buf0[BB * NN * HH];
__device__ float g_buf1[BB * NN * HH];
__device__ float g_A[BB * NN * HH];
__device__ float g_C[BB * NN * HH];
__device__ int   g_nbr[BB * NN * KK];

// ---------------- kNN: one thread per query row, register top-K ------------
// d2 = sq_i + sq_j - 2*dot  (same formula as the reference; self-dist == 0)
template <int D, int TJ>
__global__ __launch_bounds__(128) void knn_kernel(const float* __restrict__ X,
                                                  int* __restrict__ nbr) {
    const int b = blockIdx.y;
    const int i = blockIdx.x * 128 + threadIdx.x;
    const float* xb = X + (size_t)b * NN * D;

    float xi[D];
#pragma unroll
    for (int d = 0; d < D; d++) xi[d] = xb[(size_t)i * D + d];
    float sqi = 0.f;
#pragma unroll
    for (int d = 0; d < D; d++) sqi = fmaf(xi[d], xi[d], sqi);

    float dist[KK];
    int   idx[KK];
#pragma unroll
    for (int t = 0; t < KK; t++) { dist[t] = 3.4028235e38f; idx[t] = 0; }

    __shared__ float sx[TJ * D];
    __shared__ float ssq[TJ];

    for (int j0 = 0; j0 < NN; j0 += TJ) {
        __syncthreads();
        if ((D & 3) == 0) {
            const float4* src = (const float4*)(xb + (size_t)j0 * D);
            float4* dst = (float4*)sx;
            for (int t = threadIdx.x; t < TJ * D / 4; t += 128) dst[t] = src[t];
        } else {
            for (int t = threadIdx.x; t < TJ * D; t += 128)
                sx[t] = xb[(size_t)j0 * D + t];
        }
        __syncthreads();
        for (int t = threadIdx.x; t < TJ; t += 128) {
            float s = 0.f;
#pragma unroll
            for (int d = 0; d < D; d++) s = fmaf(sx[t * D + d], sx[t * D + d], s);
            ssq[t] = s;
        }
        __syncthreads();

#pragma unroll 2
        for (int jj = 0; jj < TJ; jj++) {
            float dot = 0.f;
#pragma unroll
            for (int d = 0; d < D; d++) dot = fmaf(xi[d], sx[jj * D + d], dot);
            float dd = sqi + ssq[jj] - 2.f * dot;
            if (dd < dist[KK - 1]) {
                dist[KK - 1] = dd;
                idx[KK - 1] = j0 + jj;
#pragma unroll
                for (int t = KK - 1; t > 0; t--) {
                    if (dist[t] < dist[t - 1]) {
                        float td = dist[t]; dist[t] = dist[t - 1]; dist[t - 1] = td;
                        int   ti = idx[t];  idx[t]  = idx[t - 1];  idx[t - 1]  = ti;
                    }
                }
            }
        }
    }

    int* o = nbr + ((size_t)b * NN + i) * KK;
#pragma unroll
    for (int t = 0; t < KK; t++) o[t] = idx[t];
}

// ---------------- per-node precompute: A = X@(w1_top - w1_bot)+b1, C = X@w1_bot
template <int D>
__global__ __launch_bounds__(256) void precompute_kernel(
    const float* __restrict__ X, const float* __restrict__ w1,
    const float* __restrict__ b1, float* __restrict__ A, float* __restrict__ C) {
    __shared__ float wd[D * HH];
    __shared__ float wb[D * HH];
    __shared__ float xs[64 * D];

    const int base = blockIdx.x * 64;  // linear node base over B*N
    for (int t = threadIdx.x; t < D * HH; t += 256) {
        float bot = w1[D * HH + t];
        wd[t] = w1[t] - bot;
        wb[t] = bot;
    }
    for (int t = threadIdx.x; t < 64 * D; t += 256)
        xs[t] = X[(size_t)base * D + t];
    __syncthreads();

    const int h = threadIdx.x & 63;
    const float bias = b1[h];
    for (int g = 0; g < 16; g++) {
        int nl = g * 4 + (threadIdx.x >> 6);
        float a = bias, c = 0.f;
#pragma unroll
        for (int d = 0; d < D; d++) {
            float xv = xs[nl * D + d];
            a = fmaf(xv, wd[d * HH + h], a);
            c = fmaf(xv, wb[d * HH + h], c);
        }
        A[(size_t)(base + nl) * HH + h] = a;
        C[(size_t)(base + nl) * HH + h] = c;
    }
}

// ---------------- edge aggregate + output GEMM: out = (mean_k relu(A_i+C_j)) @ wo + bo
__global__ __launch_bounds__(256) void edge_agg_kernel(
    const int* __restrict__ nbr, const float* __restrict__ A,
    const float* __restrict__ C, const float* __restrict__ wo,
    const float* __restrict__ bo, float* __restrict__ out) {
    __shared__ float swo[HH * HH];
    __shared__ float S[16][HH];
    for (int t = threadIdx.x; t < HH * HH; t += 256) swo[t] = wo[t];

    const int base = blockIdx.x * 16;  // linear node base
    const int h = threadIdx.x & 63;
    const int sub = threadIdx.x >> 6;

    for (int g = 0; g < 4; g++) {
        int nl = g * 4 + sub;
        int node = base + nl;
        int b = node >> 11;  // node / NN
        float a = A[(size_t)node * HH + h];
        const int* ji = nbr + (size_t)node * KK;
        float s = 0.f;
#pragma unroll
        for (int k2 = 0; k2 < KK; k2++) {
            int j = ji[k2];
            float c = C[(((size_t)b << 11) + j) * HH + h];
            s += fmaxf(a + c, 0.f);
        }
        S[nl][h] = s * (1.f / KK);
    }
    __syncthreads();

    for (int g = 0; g < 4; g++) {
        int nl = g * 4 + sub;
        float acc = bo[h];
#pragma unroll
        for (int hh = 0; hh < HH; hh++)
            acc = fmaf(S[nl][hh], swo[hh * HH + h], acc);
        out[(size_t)(base + nl) * HH + h] = acc;
    }
}

// ---------------- global mean pool + 2-layer head ---------------------------
__global__ __launch_bounds__(128) void head_kernel(
    const float* __restrict__ Xf, const float* __restrict__ fw1,
    const float* __restrict__ fb1, const float* __restrict__ fw2,
    const float* __restrict__ fb2, float* __restrict__ out) {
    int b = blockIdx.x;
    __shared__ float gp[2][HH];
    __shared__ float gv[HH];
    __shared__ float tv[HH];

    int h = threadIdx.x & 63;
    int half = threadIdx.x >> 6;
    float acc = 0.f;
    for (int n = half; n < NN; n += 2)
        acc += Xf[((size_t)b * NN + n) * HH + h];
    gp[half][h] = acc;
    __syncthreads();
    if (threadIdx.x < HH)
        gv[threadIdx.x] = (gp[0][threadIdx.x] + gp[1][threadIdx.x]) * (1.f / NN);
    __syncthreads();
    if (threadIdx.x < HH) {
        float a = fb1[threadIdx.x];
        for (int p = 0; p < HH; p++)
            a = fmaf(gv[p], fw1[p * HH + threadIdx.x], a);
        tv[threadIdx.x] = fmaxf(a, 0.f);
    }
    __syncthreads();
    float o = fb2[threadIdx.x];
    for (int p = 0; p < HH; p++)
        o = fmaf(tv[p], fw2[p * OUTD + threadIdx.x], o);
    out[b * OUTD + threadIdx.x] = o;
}

// ---------------- launch -----------------------------------------------------
extern "C" void kernel_launch(void* const* d_in, const int* in_sizes, int n_in,
                              void* d_out, int out_size) {
    (void)in_sizes; (void)n_in; (void)out_size;
    const float* x   = (const float*)d_in[0];
    const float* w1a[3] = {(const float*)d_in[1], (const float*)d_in[5], (const float*)d_in[9]};
    const float* b1a[3] = {(const float*)d_in[2], (const float*)d_in[6], (const float*)d_in[10]};
    const float* woa[3] = {(const float*)d_in[3], (const float*)d_in[7], (const float*)d_in[11]};
    const float* boa[3] = {(const float*)d_in[4], (const float*)d_in[8], (const float*)d_in[12]};
    const float* fw1 = (const float*)d_in[13];
    const float* fb1 = (const float*)d_in[14];
    const float* fw2 = (const float*)d_in[15];
    const float* fb2 = (const float*)d_in[16];

    float *buf0, *buf1, *Ab, *Cb; int* nbr;
    cudaGetSymbolAddress((void**)&buf0, g_buf0);
    cudaGetSymbolAddress((void**)&buf1, g_buf1);
    cudaGetSymbolAddress((void**)&Ab,   g_A);
    cudaGetSymbolAddress((void**)&Cb,   g_C);
    cudaGetSymbolAddress((void**)&nbr,  g_nbr);

    dim3 kg(NN / 128, BB);
    const int PRE_G = BB * NN / 64;
    const int AGG_G = BB * NN / 16;

    // layer 0 (D = 3)
    knn_kernel<3, 2048><<<kg, 128>>>(x, nbr);
    precompute_kernel<3><<<PRE_G, 256>>>(x, w1a[0], b1a[0], Ab, Cb);
    edge_agg_kernel<<<AGG_G, 256>>>(nbr, Ab, Cb, woa[0], boa[0], buf0);

    // layer 1 (D = 64)
    knn_kernel<64, 128><<<kg, 128>>>(buf0, nbr);
    precompute_kernel<64><<<PRE_G, 256>>>(buf0, w1a[1], b1a[1], Ab, Cb);
    edge_agg_kernel<<<AGG_G, 256>>>(nbr, Ab, Cb, woa[1], boa[1], buf1);

    // layer 2 (D = 64)
    knn_kernel<64, 128><<<kg, 128>>>(buf1, nbr);
    precompute_kernel<64><<<PRE_G, 256>>>(buf1, w1a[2], b1a[2], Ab, Cb);
    edge_agg_kernel<<<AGG_G, 256>>>(nbr, Ab, Cb, woa[2], boa[2], buf0);

    head_kernel<<<BB, 128>>>(buf0, fw1, fb1, fw2, fb2, (float*)d_out);
}

// round 2
// speedup vs baseline: 1.0632x; 1.0632x over previous
#include <cuda_runtime.h>
#include <cuda_bf16.h>
#include <cstdint>

#define BB   32
#define NN   2048
#define HH   64
#define OUTD 128
#define KK   16

// ---------------- scratch (static device globals; no runtime allocation) ----
__device__ float g_buf0[BB * NN * HH];
__device__ float g_buf1[BB * NN * HH];
__device__ float g_A[BB * NN * HH];
__device__ float g_C[BB * NN * HH];
__device__ int   g_nbr[BB * NN * KK];
__device__ __align__(16) __nv_bfloat16 g_xhi[BB * NN * HH];
__device__ __align__(16) __nv_bfloat16 g_xlo[BB * NN * HH];
__device__ float g_sq[BB * NN];

// ---------------- fp32 -> (bf16 hi, bf16 lo) split + squared norms ----------
template <int D, int DP>
__global__ __launch_bounds__(128) void convert_kernel(
    const float* __restrict__ X, __nv_bfloat16* __restrict__ Hh,
    __nv_bfloat16* __restrict__ Ll, float* __restrict__ SQ) {
    const int node = blockIdx.x * 128 + threadIdx.x;
    const float* xp = X + (size_t)node * D;
    float s = 0.f;
#pragma unroll
    for (int d = 0; d < DP; d++) {
        float v = (d < D) ? xp[d] : 0.f;
        s = fmaf(v, v, s);
        __nv_bfloat16 h = __float2bfloat16(v);
        float r = v - __bfloat162float(h);
        Hh[(size_t)node * DP + d] = h;
        Ll[(size_t)node * DP + d] = __float2bfloat16(r);
    }
    SQ[node] = s;
}

// ---------------- bf16 mma helper -------------------------------------------
__device__ __forceinline__ void mma_bf16(float* c, const uint32_t* a,
                                         uint32_t b0, uint32_t b1) {
    asm volatile(
        "mma.sync.aligned.m16n8k16.row.col.f32.bf16.bf16.f32 "
        "{%0,%1,%2,%3},{%4,%5,%6,%7},{%8,%9},{%0,%1,%2,%3};"
        : "+f"(c[0]), "+f"(c[1]), "+f"(c[2]), "+f"(c[3])
        : "r"(a[0]), "r"(a[1]), "r"(a[2]), "r"(a[3]), "r"(b0), "r"(b1));
}

// ---------------- tensor-core kNN -------------------------------------------
// Block: 64 queries x all candidates (tiles of 32). 4 warps, each warp owns 16
// query rows of the mma. Key = sq_j - 2*dot_ij (sq_i dropped: rank-invariant).
// Selection: 2 threads per query (one per 16-candidate half), register top-16,
// final merge with (key, index) tie-break == reference stable top_k semantics.
template <int DP>
__global__ __launch_bounds__(128) void knn_mma_kernel(
    const __nv_bfloat16* __restrict__ Xh, const __nv_bfloat16* __restrict__ Xl,
    const float* __restrict__ SQ, int* __restrict__ nbr) {
    constexpr int NK = DP / 16;
    constexpr int QS = DP + 8;  // padded row stride (bf16) for bank-conflict-free frags
    constexpr int OFF_QH = 0;
    constexpr int OFF_QL = OFF_QH + 64 * QS * 2;
    constexpr int OFF_CH = OFF_QL + 64 * QS * 2;
    constexpr int OFF_CL = OFF_CH + 32 * QS * 2;
    constexpr int OFF_KEY = OFF_CL + 32 * QS * 2;
    constexpr int OFF_SQC = OFF_KEY + 32 * 65 * 4;
    constexpr int TOT = OFF_SQC + 32 * 4;
    constexpr int MERGE = 64 * 33 * 4 * 2;
    constexpr int SBYTES = (TOT > MERGE ? TOT : MERGE);
    __shared__ __align__(16) char SB[SBYTES];
    __nv_bfloat16* sQh = (__nv_bfloat16*)(SB + OFF_QH);
    __nv_bfloat16* sQl = (__nv_bfloat16*)(SB + OFF_QL);
    __nv_bfloat16* sCh = (__nv_bfloat16*)(SB + OFF_CH);
    __nv_bfloat16* sCl = (__nv_bfloat16*)(SB + OFF_CL);
    float* sKey = (float*)(SB + OFF_KEY);
    float* sSqc = (float*)(SB + OFF_SQC);

    const int b = blockIdx.y;
    const int qbase = blockIdx.x * 64;
    const int tid = threadIdx.x;
    const int lane = tid & 31;
    const int warp = tid >> 5;

    // load Q tile (64 rows, padded stride)
    {
        constexpr int CH = DP / 8;  // uint4 chunks per row
        const uint4* gh = (const uint4*)(Xh + ((size_t)b * NN + qbase) * DP);
        const uint4* gl = (const uint4*)(Xl + ((size_t)b * NN + qbase) * DP);
        for (int u = tid; u < 64 * CH; u += 128) {
            int r = u / CH, c = u % CH;
            ((uint4*)(sQh + r * QS))[c] = gh[u];
            ((uint4*)(sQl + r * QS))[c] = gl[u];
        }
    }

    float bd[16];
    int bi[16];
#pragma unroll
    for (int t = 0; t < 16; t++) { bd[t] = 3.4028235e38f; bi[t] = 0; }
    const int selq = tid & 63;
    const int half = tid >> 6;
    const int ar = warp * 16 + (lane >> 2);
    const int kk0 = (lane & 3) * 2;

    for (int ct = 0; ct < NN / 32; ct++) {
        __syncthreads();
        {
            constexpr int CH = DP / 8;
            const uint4* gh = (const uint4*)(Xh + ((size_t)b * NN + ct * 32) * DP);
            const uint4* gl = (const uint4*)(Xl + ((size_t)b * NN + ct * 32) * DP);
            for (int u = tid; u < 32 * CH; u += 128) {
                int r = u / CH, c = u % CH;
                ((uint4*)(sCh + r * QS))[c] = gh[u];
                ((uint4*)(sCl + r * QS))[c] = gl[u];
            }
            if (tid < 32) sSqc[tid] = SQ[b * NN + ct * 32 + tid];
        }
        __syncthreads();

        float acc[4][4];
#pragma unroll
        for (int i = 0; i < 4; i++)
#pragma unroll
            for (int j = 0; j < 4; j++) acc[i][j] = 0.f;

#pragma unroll
        for (int ks = 0; ks < NK; ks++) {
            const int kb = ks * 16 + kk0;
            uint32_t ah[4], al[4];
            ah[0] = *(const uint32_t*)(sQh + ar * QS + kb);
            ah[1] = *(const uint32_t*)(sQh + (ar + 8) * QS + kb);
            ah[2] = *(const uint32_t*)(sQh + ar * QS + kb + 8);
            ah[3] = *(const uint32_t*)(sQh + (ar + 8) * QS + kb + 8);
            al[0] = *(const uint32_t*)(sQl + ar * QS + kb);
            al[1] = *(const uint32_t*)(sQl + (ar + 8) * QS + kb);
            al[2] = *(const uint32_t*)(sQl + ar * QS + kb + 8);
            al[3] = *(const uint32_t*)(sQl + (ar + 8) * QS + kb + 8);
#pragma unroll
            for (int nt = 0; nt < 4; nt++) {
                const int bn = nt * 8 + (lane >> 2);
                uint32_t bh0 = *(const uint32_t*)(sCh + bn * QS + kb);
                uint32_t bh1 = *(const uint32_t*)(sCh + bn * QS + kb + 8);
                uint32_t bl0 = *(const uint32_t*)(sCl + bn * QS + kb);
                uint32_t bl1 = *(const uint32_t*)(sCl + bn * QS + kb + 8);
                mma_bf16(acc[nt], ah, bh0, bh1);
                mma_bf16(acc[nt], ah, bl0, bl1);
                mma_bf16(acc[nt], al, bh0, bh1);
            }
        }
        // epilogue: key[c][q] = sq_c - 2*dot (padded stride 65)
#pragma unroll
        for (int nt = 0; nt < 4; nt++) {
            const int cl = nt * 8 + (lane & 3) * 2;
            const int row = warp * 16 + (lane >> 2);
            float s0 = sSqc[cl], s1 = sSqc[cl + 1];
            sKey[cl * 65 + row] = s0 - 2.f * acc[nt][0];
            sKey[(cl + 1) * 65 + row] = s1 - 2.f * acc[nt][1];
            sKey[cl * 65 + row + 8] = s0 - 2.f * acc[nt][2];
            sKey[(cl + 1) * 65 + row + 8] = s1 - 2.f * acc[nt][3];
        }
        __syncthreads();

        // selection: 16 candidates per thread
#pragma unroll 1
        for (int c = 0; c < 16; c++) {
            const int cl = half * 16 + c;
            float key = sKey[cl * 65 + selq];
            if (key < bd[15]) {
                bd[15] = key;
                bi[15] = ct * 32 + cl;
#pragma unroll
                for (int t = 15; t > 0; t--) {
                    if (bd[t] < bd[t - 1]) {
                        float td = bd[t]; bd[t] = bd[t - 1]; bd[t - 1] = td;
                        int ti = bi[t]; bi[t] = bi[t - 1]; bi[t - 1] = ti;
                    }
                }
            }
        }
    }

    __syncthreads();
    float* mD = (float*)SB;
    int* mI = (int*)(SB + 64 * 33 * 4);
    {
        const int base = selq * 33 + half * 16;
#pragma unroll
        for (int t = 0; t < 16; t++) { mD[base + t] = bd[t]; mI[base + t] = bi[t]; }
    }
    __syncthreads();
    if (tid < 64) {
        const float* dA = mD + tid * 33;
        const int* iA = mI + tid * 33;
        int ia = 0, ib = 16;
        int* o = nbr + ((size_t)b * NN + qbase + tid) * KK;
#pragma unroll
        for (int r = 0; r < 16; r++) {
            float da = dA[ia], db = dA[ib];
            int xa = iA[ia], xb = iA[ib];
            bool ta = (da < db) || (da == db && xa < xb);
            o[r] = ta ? xa : xb;
            if (ta) ia++; else ib++;
        }
    }
}

// ---------------- per-node precompute: A = X@(w1_top - w1_bot)+b1, C = X@w1_bot
template <int D>
__global__ __launch_bounds__(256) void precompute_kernel(
    const float* __restrict__ X, const float* __restrict__ w1,
    const float* __restrict__ b1, float* __restrict__ A, float* __restrict__ C) {
    __shared__ float wd[D * HH];
    __shared__ float wb[D * HH];
    __shared__ float xs[64 * D];

    const int base = blockIdx.x * 64;
    for (int t = threadIdx.x; t < D * HH; t += 256) {
        float bot = w1[D * HH + t];
        wd[t] = w1[t] - bot;
        wb[t] = bot;
    }
    for (int t = threadIdx.x; t < 64 * D; t += 256)
        xs[t] = X[(size_t)base * D + t];
    __syncthreads();

    const int h = threadIdx.x & 63;
    const float bias = b1[h];
    for (int g = 0; g < 16; g++) {
        int nl = g * 4 + (threadIdx.x >> 6);
        float a = bias, c = 0.f;
#pragma unroll
        for (int d = 0; d < D; d++) {
            float xv = xs[nl * D + d];
            a = fmaf(xv, wd[d * HH + h], a);
            c = fmaf(xv, wb[d * HH + h], c);
        }
        A[(size_t)(base + nl) * HH + h] = a;
        C[(size_t)(base + nl) * HH + h] = c;
    }
}

// ---------------- edge aggregate + output GEMM ------------------------------
__global__ __launch_bounds__(256) void edge_agg_kernel(
    const int* __restrict__ nbr, const float* __restrict__ A,
    const float* __restrict__ C, const float* __restrict__ wo,
    const float* __restrict__ bo, float* __restrict__ out) {
    __shared__ float swo[HH * HH];
    __shared__ float S[16][HH];
    for (int t = threadIdx.x; t < HH * HH; t += 256) swo[t] = wo[t];

    const int base = blockIdx.x * 16;
    const int h = threadIdx.x & 63;
    const int sub = threadIdx.x >> 6;

    for (int g = 0; g < 4; g++) {
        int nl = g * 4 + sub;
        int node = base + nl;
        int b = node >> 11;
        float a = A[(size_t)node * HH + h];
        const int* ji = nbr + (size_t)node * KK;
        float s = 0.f;
#pragma unroll
        for (int k2 = 0; k2 < KK; k2++) {
            int j = ji[k2];
            float c = C[(((size_t)b << 11) + j) * HH + h];
            s += fmaxf(a + c, 0.f);
        }
        S[nl][h] = s * (1.f / KK);
    }
    __syncthreads();

    for (int g = 0; g < 4; g++) {
        int nl = g * 4 + sub;
        float acc = bo[h];
#pragma unroll
        for (int hh = 0; hh < HH; hh++)
            acc = fmaf(S[nl][hh], swo[hh * HH + h], acc);
        out[(size_t)(base + nl) * HH + h] = acc;
    }
}

// ---------------- global mean pool + 2-layer head ---------------------------
__global__ __launch_bounds__(128) void head_kernel(
    const float* __restrict__ Xf, const float* __restrict__ fw1,
    const float* __restrict__ fb1, const float* __restrict__ fw2,
    const float* __restrict__ fb2, float* __restrict__ out) {
    int b = blockIdx.x;
    __shared__ float gp[2][HH];
    __shared__ float gv[HH];
    __shared__ float tv[HH];

    int h = threadIdx.x & 63;
    int half = threadIdx.x >> 6;
    float acc = 0.f;
    for (int n = half; n < NN; n += 2)
        acc += Xf[((size_t)b * NN + n) * HH + h];
    gp[half][h] = acc;
    __syncthreads();
    if (threadIdx.x < HH)
        gv[threadIdx.x] = (gp[0][threadIdx.x] + gp[1][threadIdx.x]) * (1.f / NN);
    __syncthreads();
    if (threadIdx.x < HH) {
        float a = fb1[threadIdx.x];
        for (int p = 0; p < HH; p++)
            a = fmaf(gv[p], fw1[p * HH + threadIdx.x], a);
        tv[threadIdx.x] = fmaxf(a, 0.f);
    }
    __syncthreads();
    float o = fb2[threadIdx.x];
    for (int p = 0; p < HH; p++)
        o = fmaf(tv[p], fw2[p * OUTD + threadIdx.x], o);
    out[b * OUTD + threadIdx.x] = o;
}

// ---------------- launch -----------------------------------------------------
extern "C" void kernel_launch(void* const* d_in, const int* in_sizes, int n_in,
                              void* d_out, int out_size) {
    (void)in_sizes; (void)n_in; (void)out_size;
    const float* x = (const float*)d_in[0];
    const float* w1a[3] = {(const float*)d_in[1], (const float*)d_in[5], (const float*)d_in[9]};
    const float* b1a[3] = {(const float*)d_in[2], (const float*)d_in[6], (const float*)d_in[10]};
    const float* woa[3] = {(const float*)d_in[3], (const float*)d_in[7], (const float*)d_in[11]};
    const float* boa[3] = {(const float*)d_in[4], (const float*)d_in[8], (const float*)d_in[12]};
    const float* fw1 = (const float*)d_in[13];
    const float* fb1 = (const float*)d_in[14];
    const float* fw2 = (const float*)d_in[15];
    const float* fb2 = (const float*)d_in[16];

    float *buf0, *buf1, *Ab, *Cb, *sq;
    int* nbr;
    __nv_bfloat16 *xhi, *xlo;
    cudaGetSymbolAddress((void**)&buf0, g_buf0);
    cudaGetSymbolAddress((void**)&buf1, g_buf1);
    cudaGetSymbolAddress((void**)&Ab, g_A);
    cudaGetSymbolAddress((void**)&Cb, g_C);
    cudaGetSymbolAddress((void**)&nbr, g_nbr);
    cudaGetSymbolAddress((void**)&xhi, g_xhi);
    cudaGetSymbolAddress((void**)&xlo, g_xlo);
    cudaGetSymbolAddress((void**)&sq, g_sq);

    const int CONV_G = BB * NN / 128;
    const dim3 kg(NN / 64, BB);
    const int PRE_G = BB * NN / 64;
    const int AGG_G = BB * NN / 16;

    // layer 0 (D = 3, padded to 16)
    convert_kernel<3, 16><<<CONV_G, 128>>>(x, xhi, xlo, sq);
    knn_mma_kernel<16><<<kg, 128>>>(xhi, xlo, sq, nbr);
    precompute_kernel<3><<<PRE_G, 256>>>(x, w1a[0], b1a[0], Ab, Cb);
    edge_agg_kernel<<<AGG_G, 256>>>(nbr, Ab, Cb, woa[0], boa[0], buf0);

    // layer 1 (D = 64)
    convert_kernel<64, 64><<<CONV_G, 128>>>(buf0, xhi, xlo, sq);
    knn_mma_kernel<64><<<kg, 128>>>(xhi, xlo, sq, nbr);
    precompute_kernel<64><<<PRE_G, 256>>>(buf0, w1a[1], b1a[1], Ab, Cb);
    edge_agg_kernel<<<AGG_G, 256>>>(nbr, Ab, Cb, woa[1], boa[1], buf1);

    // layer 2 (D = 64)
    convert_kernel<64, 64><<<CONV_G, 128>>>(buf1, xhi, xlo, sq);
    knn_mma_kernel<64><<<kg, 128>>>(xhi, xlo, sq, nbr);
    precompute_kernel<64><<<PRE_G, 256>>>(buf1, w1a[2], b1a[2], Ab, Cb);
    edge_agg_kernel<<<AGG_G, 256>>>(nbr, Ab, Cb, woa[2], boa[2], buf0);

    head_kernel<<<BB, 128>>>(buf0, fw1, fb1, fw2, fb2, (float*)d_out);
}

// round 3
// speedup vs baseline: 1.6185x; 1.5223x over previous
#include <cuda_runtime.h>
#include <cuda_bf16.h>
#include <cstdint>

#define BB   32
#define NN   2048
#define HH   64
#define OUTD 128
#define KK   16

// ---------------- scratch (static device globals; no runtime allocation) ----
__device__ float g_buf0[BB * NN * HH];
__device__ float g_buf1[BB * NN * HH];
__device__ float g_A[BB * NN * HH];
__device__ float g_C[BB * NN * HH];
__device__ int   g_nbr[BB * NN * KK];
__device__ __align__(16) __nv_bfloat16 g_xhi[BB * NN * HH];
__device__ __align__(16) __nv_bfloat16 g_xlo[BB * NN * HH];
__device__ float g_sq[BB * NN];

// ---------------- fp32 -> (bf16 hi, bf16 lo) split + squared norms ----------
template <int D, int DP>
__global__ __launch_bounds__(128) void convert_kernel(
    const float* __restrict__ X, __nv_bfloat16* __restrict__ Hh,
    __nv_bfloat16* __restrict__ Ll, float* __restrict__ SQ) {
    const int node = blockIdx.x * 128 + threadIdx.x;
    const float* xp = X + (size_t)node * D;
    float s = 0.f;
#pragma unroll
    for (int d = 0; d < DP; d++) {
        float v = (d < D) ? xp[d] : 0.f;
        s = fmaf(v, v, s);
        __nv_bfloat16 h = __float2bfloat16(v);
        float r = v - __bfloat162float(h);
        Hh[(size_t)node * DP + d] = h;
        Ll[(size_t)node * DP + d] = __float2bfloat16(r);
    }
    SQ[node] = s;
}

// ---------------- asm helpers ------------------------------------------------
__device__ __forceinline__ void mma_bf16(float* c, const uint32_t* a,
                                         uint32_t b0, uint32_t b1) {
    asm volatile(
        "mma.sync.aligned.m16n8k16.row.col.f32.bf16.bf16.f32 "
        "{%0,%1,%2,%3},{%4,%5,%6,%7},{%8,%9},{%0,%1,%2,%3};"
        : "+f"(c[0]), "+f"(c[1]), "+f"(c[2]), "+f"(c[3])
        : "r"(a[0]), "r"(a[1]), "r"(a[2]), "r"(a[3]), "r"(b0), "r"(b1));
}
__device__ __forceinline__ void ldsm4(uint32_t* r, uint32_t addr) {
    asm volatile("ldmatrix.sync.aligned.m8n8.x4.shared.b16 {%0,%1,%2,%3}, [%4];"
                 : "=r"(r[0]), "=r"(r[1]), "=r"(r[2]), "=r"(r[3]) : "r"(addr));
}
#define CPA16(d, s) asm volatile("cp.async.ca.shared.global [%0], [%1], 16;" :: "r"(d), "l"(s) : "memory")
#define CPCOMMIT()  asm volatile("cp.async.commit_group;" ::: "memory")
#define CPWAIT()    asm volatile("cp.async.wait_group 0;" ::: "memory")

// ---------------- tensor-core kNN v2 ----------------------------------------
// 64 queries/block, 64-candidate tiles, ldmatrix frags, cp.async overlap,
// buffered selection with warp-synchronized flushes.
template <int DP>
__global__ __launch_bounds__(128) void knn_mma_kernel(
    const __nv_bfloat16* __restrict__ Xh, const __nv_bfloat16* __restrict__ Xl,
    const float* __restrict__ SQ, int* __restrict__ nbr) {
    constexpr int NK = DP / 16;
    constexpr int QS = DP + 8;      // bf16 row stride
    constexpr int CS = 68;          // key row stride (floats)
    constexpr int NT = NN / 64;     // 32 tiles
    constexpr int CH = DP / 8;      // uint4 chunks per row

    extern __shared__ __align__(16) char SB[];
    __nv_bfloat16* sQh = (__nv_bfloat16*)(SB);
    __nv_bfloat16* sQl = (__nv_bfloat16*)(SB + 64 * QS * 2);
    __nv_bfloat16* sCh = (__nv_bfloat16*)(SB + 64 * QS * 4);
    __nv_bfloat16* sCl = (__nv_bfloat16*)(SB + 64 * QS * 6);
    float* sKey = (float*)(SB + 64 * QS * 8);
    float* sSqc = (float*)(SB + 64 * QS * 8 + 64 * CS * 4);
    uint2* sBuf = (uint2*)(SB + 64 * QS * 8 + 64 * CS * 4 + 256);

    const int b = blockIdx.y;
    const int qbase = blockIdx.x * 64;
    const int tid = threadIdx.x;
    const int lane = tid & 31;
    const int warp = tid >> 5;

    // ---- load Q tile (once) ----
    {
        const uint4* gh = (const uint4*)(Xh + ((size_t)b * NN + qbase) * DP);
        const uint4* gl = (const uint4*)(Xl + ((size_t)b * NN + qbase) * DP);
        for (int u = tid; u < 64 * CH; u += 128) {
            int r = u / CH, c = u % CH;
            *(uint4*)(sQh + r * QS + c * 8) = gh[u];
            *(uint4*)(sQl + r * QS + c * 8) = gl[u];
        }
    }

    const uint32_t sCh_s = (uint32_t)__cvta_generic_to_shared(sCh);
    const uint32_t sCl_s = (uint32_t)__cvta_generic_to_shared(sCl);
    const uint32_t sQh_s = (uint32_t)__cvta_generic_to_shared(sQh);
    const uint32_t sQl_s = (uint32_t)__cvta_generic_to_shared(sQl);

    // ldmatrix lane->tile mapping (same for A rows and B rows)
    const int lrow = (lane & 7) + ((lane >> 3) & 1) * 8;
    const int lcolk = ((lane >> 4) & 1) * 8;

    // ---- selection state ----
    float bd[16];
    int bi[16];
#pragma unroll
    for (int t = 0; t < 16; t++) { bd[t] = 3.4028235e38f; bi[t] = 0; }
    float thr = 3.4028235e38f;
    int cnt = 0;
    const int selq = tid & 63;
    const int half = tid >> 6;

    auto loadC = [&](int ct) {
        const uint4* gh = (const uint4*)(Xh + ((size_t)b * NN + ct * 64) * DP);
        const uint4* gl = (const uint4*)(Xl + ((size_t)b * NN + ct * 64) * DP);
#pragma unroll
        for (int u = tid; u < 64 * CH; u += 128) {
            int r = u / CH, c = u % CH;
            CPA16(sCh_s + (r * QS + c * 8) * 2, gh + u);
            CPA16(sCl_s + (r * QS + c * 8) * 2, gl + u);
        }
        if (tid < 64) sSqc[tid] = SQ[b * NN + ct * 64 + tid];
        CPCOMMIT();
    };

    auto mma_tile = [&]() {
        float acc[8][4];
#pragma unroll
        for (int i = 0; i < 8; i++)
#pragma unroll
            for (int j = 0; j < 4; j++) acc[i][j] = 0.f;

#pragma unroll
        for (int ks = 0; ks < NK; ks++) {
            const int kc = ks * 16 + lcolk;
            uint32_t ah[4], al[4];
            ldsm4(ah, sQh_s + ((warp * 16 + lrow) * QS + kc) * 2);
            ldsm4(al, sQl_s + ((warp * 16 + lrow) * QS + kc) * 2);
#pragma unroll
            for (int cp = 0; cp < 4; cp++) {
                uint32_t bh[4], bl[4];
                ldsm4(bh, sCh_s + ((cp * 16 + lrow) * QS + kc) * 2);
                ldsm4(bl, sCl_s + ((cp * 16 + lrow) * QS + kc) * 2);
                mma_bf16(acc[2 * cp], ah, bh[0], bh[2]);
                mma_bf16(acc[2 * cp], ah, bl[0], bl[2]);
                mma_bf16(acc[2 * cp], al, bh[0], bh[2]);
                mma_bf16(acc[2 * cp + 1], ah, bh[1], bh[3]);
                mma_bf16(acc[2 * cp + 1], ah, bl[1], bl[3]);
                mma_bf16(acc[2 * cp + 1], al, bh[1], bh[3]);
            }
        }
        // epilogue: key[q][c] = sq_c - 2*dot
        const int r0 = warp * 16 + (lane >> 2);
#pragma unroll
        for (int nt = 0; nt < 8; nt++) {
            const int n0 = nt * 8 + (lane & 3) * 2;
            float2 sq2 = *(const float2*)(sSqc + n0);
            float2 v0 = make_float2(sq2.x - 2.f * acc[nt][0], sq2.y - 2.f * acc[nt][1]);
            float2 v1 = make_float2(sq2.x - 2.f * acc[nt][2], sq2.y - 2.f * acc[nt][3]);
            *(float2*)(sKey + r0 * CS + n0) = v0;
            *(float2*)(sKey + (r0 + 8) * CS + n0) = v1;
        }
    };

    auto flush = [&]() {
        int n = cnt;
        cnt = 0;
#pragma unroll 1
        for (int i = 0; i < n; i++) {
            uint2 u = sBuf[tid * 8 + i];
            float k = __uint_as_float(u.x);
            int id = (int)u.y;
            if (k < bd[15]) {
                bd[15] = k; bi[15] = id;
#pragma unroll
                for (int t = 15; t > 0; t--) {
                    if (bd[t] < bd[t - 1]) {
                        float td = bd[t]; bd[t] = bd[t - 1]; bd[t - 1] = td;
                        int ti = bi[t]; bi[t] = bi[t - 1]; bi[t - 1] = ti;
                    }
                }
            }
        }
        thr = bd[15];
    };

    auto select = [&](int ct) {
        const float* kp = sKey + selq * CS + half * 32;
        const int base = ct * 64 + half * 32;
#pragma unroll 1
        for (int g = 0; g < 8; g++) {
            if (__any_sync(0xffffffffu, cnt >= 4)) flush();
            float4 v = *(const float4*)(kp + g * 4);
            const int ib = base + g * 4;
            if (v.x < thr) { sBuf[tid * 8 + cnt] = make_uint2(__float_as_uint(v.x), ib); cnt++; }
            if (v.y < thr) { sBuf[tid * 8 + cnt] = make_uint2(__float_as_uint(v.y), ib + 1); cnt++; }
            if (v.z < thr) { sBuf[tid * 8 + cnt] = make_uint2(__float_as_uint(v.z), ib + 2); cnt++; }
            if (v.w < thr) { sBuf[tid * 8 + cnt] = make_uint2(__float_as_uint(v.w), ib + 3); cnt++; }
        }
    };

    // ---- pipeline ----
    loadC(0);
    CPWAIT();
    __syncthreads();
    mma_tile();
#pragma unroll 1
    for (int ct = 1; ct < NT; ct++) {
        __syncthreads();
        loadC(ct);
        select(ct - 1);
        CPWAIT();
        __syncthreads();
        mma_tile();
    }
    __syncthreads();
    select(NT - 1);
    flush();
    __syncthreads();

    // ---- merge two halves (stable, index tie-break) ----
    float* mD = sKey;
    int* mI = (int*)(sKey + 64 * 33);
    {
        const int base = selq * 33 + half * 16;
#pragma unroll
        for (int t = 0; t < 16; t++) { mD[base + t] = bd[t]; mI[base + t] = bi[t]; }
    }
    __syncthreads();
    if (tid < 64) {
        const float* dA = mD + tid * 33;
        const int* iA = mI + tid * 33;
        int ia = 0, ib2 = 16;
        int* o = nbr + ((size_t)b * NN + qbase + tid) * KK;
#pragma unroll
        for (int r = 0; r < 16; r++) {
            float da = dA[ia], db = dA[ib2];
            int xa = iA[ia], xb = iA[ib2];
            bool ta = (da < db) || (da == db && xa < xb);
            o[r] = ta ? xa : xb;
            if (ta) ia++; else ib2++;
        }
    }
}

// ---------------- per-node precompute: A = X@(w1_top - w1_bot)+b1, C = X@w1_bot
template <int D>
__global__ __launch_bounds__(256) void precompute_kernel(
    const float* __restrict__ X, const float* __restrict__ w1,
    const float* __restrict__ b1, float* __restrict__ A, float* __restrict__ C) {
    __shared__ float wd[D * HH];
    __shared__ float wb[D * HH];
    __shared__ float xs[64 * D];

    const int base = blockIdx.x * 64;
    for (int t = threadIdx.x; t < D * HH; t += 256) {
        float bot = w1[D * HH + t];
        wd[t] = w1[t] - bot;
        wb[t] = bot;
    }
    for (int t = threadIdx.x; t < 64 * D; t += 256)
        xs[t] = X[(size_t)base * D + t];
    __syncthreads();

    const int h = threadIdx.x & 63;
    const float bias = b1[h];
    for (int g = 0; g < 16; g++) {
        int nl = g * 4 + (threadIdx.x >> 6);
        float a = bias, c = 0.f;
#pragma unroll
        for (int d = 0; d < D; d++) {
            float xv = xs[nl * D + d];
            a = fmaf(xv, wd[d * HH + h], a);
            c = fmaf(xv, wb[d * HH + h], c);
        }
        A[(size_t)(base + nl) * HH + h] = a;
        C[(size_t)(base + nl) * HH + h] = c;
    }
}

// ---------------- edge aggregate + output GEMM ------------------------------
__global__ __launch_bounds__(256) void edge_agg_kernel(
    const int* __restrict__ nbr, const float* __restrict__ A,
    const float* __restrict__ C, const float* __restrict__ wo,
    const float* __restrict__ bo, float* __restrict__ out) {
    __shared__ float swo[HH * HH];
    __shared__ float S[16][HH];
    for (int t = threadIdx.x; t < HH * HH; t += 256) swo[t] = wo[t];

    const int base = blockIdx.x * 16;
    const int h = threadIdx.x & 63;
    const int sub = threadIdx.x >> 6;

    for (int g = 0; g < 4; g++) {
        int nl = g * 4 + sub;
        int node = base + nl;
        int b = node >> 11;
        float a = A[(size_t)node * HH + h];
        const int* ji = nbr + (size_t)node * KK;
        float s = 0.f;
#pragma unroll
        for (int k2 = 0; k2 < KK; k2++) {
            int j = ji[k2];
            float c = C[(((size_t)b << 11) + j) * HH + h];
            s += fmaxf(a + c, 0.f);
        }
        S[nl][h] = s * (1.f / KK);
    }
    __syncthreads();

    for (int g = 0; g < 4; g++) {
        int nl = g * 4 + sub;
        float acc = bo[h];
#pragma unroll
        for (int hh = 0; hh < HH; hh++)
            acc = fmaf(S[nl][hh], swo[hh * HH + h], acc);
        out[(size_t)(base + nl) * HH + h] = acc;
    }
}

// ---------------- global mean pool + 2-layer head ---------------------------
__global__ __launch_bounds__(128) void head_kernel(
    const float* __restrict__ Xf, const float* __restrict__ fw1,
    const float* __restrict__ fb1, const float* __restrict__ fw2,
    const float* __restrict__ fb2, float* __restrict__ out) {
    int b = blockIdx.x;
    __shared__ float gp[2][HH];
    __shared__ float gv[HH];
    __shared__ float tv[HH];

    int h = threadIdx.x & 63;
    int half = threadIdx.x >> 6;
    float acc = 0.f;
    for (int n = half; n < NN; n += 2)
        acc += Xf[((size_t)b * NN + n) * HH + h];
    gp[half][h] = acc;
    __syncthreads();
    if (threadIdx.x < HH)
        gv[threadIdx.x] = (gp[0][threadIdx.x] + gp[1][threadIdx.x]) * (1.f / NN);
    __syncthreads();
    if (threadIdx.x < HH) {
        float a = fb1[threadIdx.x];
        for (int p = 0; p < HH; p++)
            a = fmaf(gv[p], fw1[p * HH + threadIdx.x], a);
        tv[threadIdx.x] = fmaxf(a, 0.f);
    }
    __syncthreads();
    float o = fb2[threadIdx.x];
    for (int p = 0; p < HH; p++)
        o = fmaf(tv[p], fw2[p * OUTD + threadIdx.x], o);
    out[b * OUTD + threadIdx.x] = o;
}

// ---------------- launch -----------------------------------------------------
static inline int knn_smem_bytes(int DPv) {
    int QSv = DPv + 8;
    return 64 * QSv * 2 * 4 + 64 * 68 * 4 + 256 + 128 * 8 * 8;
}

extern "C" void kernel_launch(void* const* d_in, const int* in_sizes, int n_in,
                              void* d_out, int out_size) {
    (void)in_sizes; (void)n_in; (void)out_size;
    const float* x = (const float*)d_in[0];
    const float* w1a[3] = {(const float*)d_in[1], (const float*)d_in[5], (const float*)d_in[9]};
    const float* b1a[3] = {(const float*)d_in[2], (const float*)d_in[6], (const float*)d_in[10]};
    const float* woa[3] = {(const float*)d_in[3], (const float*)d_in[7], (const float*)d_in[11]};
    const float* boa[3] = {(const float*)d_in[4], (const float*)d_in[8], (const float*)d_in[12]};
    const float* fw1 = (const float*)d_in[13];
    const float* fb1 = (const float*)d_in[14];
    const float* fw2 = (const float*)d_in[15];
    const float* fb2 = (const float*)d_in[16];

    float *buf0, *buf1, *Ab, *Cb, *sq;
    int* nbr;
    __nv_bfloat16 *xhi, *xlo;
    cudaGetSymbolAddress((void**)&buf0, g_buf0);
    cudaGetSymbolAddress((void**)&buf1, g_buf1);
    cudaGetSymbolAddress((void**)&Ab, g_A);
    cudaGetSymbolAddress((void**)&Cb, g_C);
    cudaGetSymbolAddress((void**)&nbr, g_nbr);
    cudaGetSymbolAddress((void**)&xhi, g_xhi);
    cudaGetSymbolAddress((void**)&xlo, g_xlo);
    cudaGetSymbolAddress((void**)&sq, g_sq);

    const int smem16 = knn_smem_bytes(16);
    const int smem64 = knn_smem_bytes(64);
    cudaFuncSetAttribute(knn_mma_kernel<16>, cudaFuncAttributeMaxDynamicSharedMemorySize, smem16);
    cudaFuncSetAttribute(knn_mma_kernel<64>, cudaFuncAttributeMaxDynamicSharedMemorySize, smem64);

    const int CONV_G = BB * NN / 128;
    const dim3 kg(NN / 64, BB);
    const int PRE_G = BB * NN / 64;
    const int AGG_G = BB * NN / 16;

    // layer 0 (D = 3, padded to 16)
    convert_kernel<3, 16><<<CONV_G, 128>>>(x, xhi, xlo, sq);
    knn_mma_kernel<16><<<kg, 128, smem16>>>(xhi, xlo, sq, nbr);
    precompute_kernel<3><<<PRE_G, 256>>>(x, w1a[0], b1a[0], Ab, Cb);
    edge_agg_kernel<<<AGG_G, 256>>>(nbr, Ab, Cb, woa[0], boa[0], buf0);

    // layer 1 (D = 64)
    convert_kernel<64, 64><<<CONV_G, 128>>>(buf0, xhi, xlo, sq);
    knn_mma_kernel<64><<<kg, 128, smem64>>>(xhi, xlo, sq, nbr);
    precompute_kernel<64><<<PRE_G, 256>>>(buf0, w1a[1], b1a[1], Ab, Cb);
    edge_agg_kernel<<<AGG_G, 256>>>(nbr, Ab, Cb, woa[1], boa[1], buf1);

    // layer 2 (D = 64)
    convert_kernel<64, 64><<<CONV_G, 128>>>(buf1, xhi, xlo, sq);
    knn_mma_kernel<64><<<kg, 128, smem64>>>(xhi, xlo, sq, nbr);
    precompute_kernel<64><<<PRE_G, 256>>>(buf1, w1a[2], b1a[2], Ab, Cb);
    edge_agg_kernel<<<AGG_G, 256>>>(nbr, Ab, Cb, woa[2], boa[2], buf0);

    head_kernel<<<BB, 128>>>(buf0, fw1, fb1, fw2, fb2, (float*)d_out);
}